// round 1
// baseline (speedup 1.0000x reference)
#include <cuda_runtime.h>

#define BB 32
#define CC 256
#define HWL 3136           // 56*56
#define HID 32
#define KK 2
#define NPLANE (BB*CC)     // 8192

// Scratch (device globals — no allocation allowed in kernel_launch)
__device__ float g_pooled[NPLANE];
__device__ float g_a[KK * NPLANE];
__device__ float g_bc[KK * NPLANE];

// ---------------------------------------------------------------------------
// Kernel 1: mean over H*W per (b,c) plane. One CTA per plane, float4 loads.
// ---------------------------------------------------------------------------
__global__ __launch_bounds__(256) void pool_kernel(const float* __restrict__ x) {
    const int plane = blockIdx.x;
    const float4* xp = reinterpret_cast<const float4*>(x + (size_t)plane * HWL);
    float s = 0.f;
#pragma unroll 4
    for (int i = threadIdx.x; i < HWL / 4; i += 256) {
        float4 v = __ldg(&xp[i]);
        s += (v.x + v.y) + (v.z + v.w);
    }
    // intra-warp reduce
#pragma unroll
    for (int o = 16; o > 0; o >>= 1) s += __shfl_xor_sync(0xffffffffu, s, o);
    __shared__ float ws[8];
    const int lane = threadIdx.x & 31;
    const int w = threadIdx.x >> 5;
    if (lane == 0) ws[w] = s;
    __syncthreads();
    if (threadIdx.x < 8) {
        s = ws[threadIdx.x];
#pragma unroll
        for (int o = 4; o > 0; o >>= 1) s += __shfl_xor_sync(0xffu, s, o);
        if (threadIdx.x == 0) g_pooled[plane] = s * (1.0f / HWL);
    }
}

// ---------------------------------------------------------------------------
// Kernel 2: tiny MLP -> per-(k,b,c) affine coefficients.
// Grid = K*B = 64 blocks, 256 threads. Each block (k,b):
//   threads 0..31 compute h[b][j] = relu(pooled[b] . fc1_w[j] + fc1_b[j])
//   then every thread c computes delta at o=2c (alpha) and o=2c+1 (beta).
// ---------------------------------------------------------------------------
__global__ __launch_bounds__(256) void coef_kernel(const float* __restrict__ fc1_w,
                                                   const float* __restrict__ fc1_b,
                                                   const float* __restrict__ fc2_w,
                                                   const float* __restrict__ fc2_b) {
    const int k = blockIdx.x >> 5;   // 0..1
    const int b = blockIdx.x & 31;   // 0..31

    __shared__ float p_s[CC];
    __shared__ float h_s[HID];

    for (int i = threadIdx.x; i < CC; i += 256) p_s[i] = g_pooled[b * CC + i];
    __syncthreads();

    if (threadIdx.x < HID) {
        const float* wrow = fc1_w + threadIdx.x * CC;
        float acc = fc1_b[threadIdx.x];
#pragma unroll 8
        for (int c2 = 0; c2 < CC; c2++) acc = fmaf(p_s[c2], wrow[c2], acc);
        h_s[threadIdx.x] = fmaxf(acc, 0.0f);
    }
    __syncthreads();

    const int c = threadIdx.x;  // 0..255
    const float* w0 = fc2_w + ((size_t)k * (2 * CC) + 2 * c) * HID;
    const float* w1 = w0 + HID;
    float d0 = fc2_b[k * 2 * CC + 2 * c];
    float d1 = fc2_b[k * 2 * CC + 2 * c + 1];
#pragma unroll
    for (int j = 0; j < HID; j++) {
        float hj = h_s[j];
        d0 = fmaf(w0[j], hj, d0);
        d1 = fmaf(w1[j], hj, d1);
    }
    // 2*sigmoid(z) - 1 == tanh(z/2)
    d0 = tanhf(0.5f * d0);
    d1 = tanhf(0.5f * d1);
    const float init = (k == 0) ? 1.0f : 0.0f;
    const int idx = (k * BB + b) * CC + c;
    g_a[idx]  = init + 1.0f * d0;   // LAMBDA_ALPHA = 1.0
    g_bc[idx] = init + 0.5f * d1;   // LAMBDA_BETA  = 0.5
}

// ---------------------------------------------------------------------------
// Kernel 3: out = max_k (x*a_k + b_k), per plane. Float4 streaming.
// ---------------------------------------------------------------------------
__global__ __launch_bounds__(256) void apply_kernel(const float* __restrict__ x,
                                                    float* __restrict__ out) {
    const int plane = blockIdx.x;   // == b*CC + c, matches coef index for k=0
    const float a0 = g_a[plane];
    const float c0 = g_bc[plane];
    const float a1 = g_a[NPLANE + plane];
    const float c1 = g_bc[NPLANE + plane];

    const float4* xp = reinterpret_cast<const float4*>(x + (size_t)plane * HWL);
    float4* op = reinterpret_cast<float4*>(out + (size_t)plane * HWL);
#pragma unroll 4
    for (int i = threadIdx.x; i < HWL / 4; i += 256) {
        float4 v = xp[i];
        float4 r;
        r.x = fmaxf(fmaf(v.x, a0, c0), fmaf(v.x, a1, c1));
        r.y = fmaxf(fmaf(v.y, a0, c0), fmaf(v.y, a1, c1));
        r.z = fmaxf(fmaf(v.z, a0, c0), fmaf(v.z, a1, c1));
        r.w = fmaxf(fmaf(v.w, a0, c0), fmaf(v.w, a1, c1));
        op[i] = r;
    }
}

extern "C" void kernel_launch(void* const* d_in, const int* in_sizes, int n_in,
                              void* d_out, int out_size) {
    const float* x      = (const float*)d_in[0];
    const float* fc1_w  = (const float*)d_in[1];
    const float* fc1_b  = (const float*)d_in[2];
    const float* fc2_w  = (const float*)d_in[3];
    const float* fc2_b  = (const float*)d_in[4];
    float* out = (float*)d_out;

    pool_kernel<<<NPLANE, 256>>>(x);
    coef_kernel<<<KK * BB, 256>>>(fc1_w, fc1_b, fc2_w, fc2_b);
    apply_kernel<<<NPLANE, 256>>>(x, out);
}

// round 2
// speedup vs baseline: 1.0638x; 1.0638x over previous
#include <cuda_runtime.h>

#define BB 32
#define CC 256
#define HWL 3136           // 56*56
#define HW4 784            // HWL/4
#define HID 32
#define KK 2
#define NPLANE (BB*CC)     // 8192

// Scratch (device globals — no allocation allowed in kernel_launch)
__device__ float g_pooled[NPLANE];
__device__ float g_a[KK * NPLANE];
__device__ float g_bc[KK * NPLANE];

// ---------------------------------------------------------------------------
// Kernel 1: mean over H*W per (b,c) plane. ONE WARP per plane.
// CTA = 256 threads = 8 warps = 8 planes. Grid = 1024.
// Each lane streams ~24 float4 with deep unroll -> high MLP, pure shfl reduce.
// ---------------------------------------------------------------------------
__global__ __launch_bounds__(256) void pool_kernel(const float* __restrict__ x) {
    const int warp = (blockIdx.x << 3) | (threadIdx.x >> 5);  // plane id
    const int lane = threadIdx.x & 31;
    const float4* xp = reinterpret_cast<const float4*>(x + (size_t)warp * HWL);

    // 784 = 24*32 + 16. Main body: 24 iters, unrolled x8 -> 3 batches of 8
    // independent loads per lane.
    float s = 0.f;
    int i = lane;
#pragma unroll 8
    for (int it = 0; it < 24; it++, i += 32) {
        float4 v = __ldg(&xp[i]);
        s += (v.x + v.y) + (v.z + v.w);
    }
    if (lane < 16) {
        float4 v = __ldg(&xp[768 + lane]);
        s += (v.x + v.y) + (v.z + v.w);
    }
#pragma unroll
    for (int o = 16; o > 0; o >>= 1) s += __shfl_xor_sync(0xffffffffu, s, o);
    if (lane == 0) g_pooled[warp] = s * (1.0f / HWL);
}

// ---------------------------------------------------------------------------
// Kernel 2: tiny MLP -> per-(k,b,c) affine coefficients.
// Grid = K*B = 64 blocks, 256 threads.
// ---------------------------------------------------------------------------
__global__ __launch_bounds__(256) void coef_kernel(const float* __restrict__ fc1_w,
                                                   const float* __restrict__ fc1_b,
                                                   const float* __restrict__ fc2_w,
                                                   const float* __restrict__ fc2_b) {
    const int k = blockIdx.x >> 5;   // 0..1
    const int b = blockIdx.x & 31;   // 0..31

    __shared__ float p_s[CC];
    __shared__ float h_s[HID];

    for (int i = threadIdx.x; i < CC; i += 256) p_s[i] = g_pooled[b * CC + i];
    __syncthreads();

    if (threadIdx.x < HID) {
        const float* wrow = fc1_w + threadIdx.x * CC;
        float acc = fc1_b[threadIdx.x];
#pragma unroll 8
        for (int c2 = 0; c2 < CC; c2++) acc = fmaf(p_s[c2], wrow[c2], acc);
        h_s[threadIdx.x] = fmaxf(acc, 0.0f);
    }
    __syncthreads();

    const int c = threadIdx.x;  // 0..255
    const float* w0 = fc2_w + ((size_t)k * (2 * CC) + 2 * c) * HID;
    const float* w1 = w0 + HID;
    float d0 = fc2_b[k * 2 * CC + 2 * c];
    float d1 = fc2_b[k * 2 * CC + 2 * c + 1];
#pragma unroll
    for (int j = 0; j < HID; j++) {
        float hj = h_s[j];
        d0 = fmaf(w0[j], hj, d0);
        d1 = fmaf(w1[j], hj, d1);
    }
    // 2*sigmoid(z) - 1 == tanh(z/2)
    d0 = tanhf(0.5f * d0);
    d1 = tanhf(0.5f * d1);
    const float init = (k == 0) ? 1.0f : 0.0f;
    const int idx = (k * BB + b) * CC + c;
    g_a[idx]  = init + 1.0f * d0;   // LAMBDA_ALPHA = 1.0
    g_bc[idx] = init + 0.5f * d1;   // LAMBDA_BETA  = 0.5
}

// ---------------------------------------------------------------------------
// Kernel 3: out = max_k (x*a_k + b_k). ONE WARP per plane, float4 streaming.
// ---------------------------------------------------------------------------
__global__ __launch_bounds__(256) void apply_kernel(const float* __restrict__ x,
                                                    float* __restrict__ out) {
    const int plane = (blockIdx.x << 3) | (threadIdx.x >> 5);
    const int lane = threadIdx.x & 31;

    const float a0 = g_a[plane];
    const float c0 = g_bc[plane];
    const float a1 = g_a[NPLANE + plane];
    const float c1 = g_bc[NPLANE + plane];

    const float4* xp = reinterpret_cast<const float4*>(x + (size_t)plane * HWL);
    float4* op = reinterpret_cast<float4*>(out + (size_t)plane * HWL);

    int i = lane;
#pragma unroll 8
    for (int it = 0; it < 24; it++, i += 32) {
        float4 v = xp[i];
        float4 r;
        r.x = fmaxf(fmaf(v.x, a0, c0), fmaf(v.x, a1, c1));
        r.y = fmaxf(fmaf(v.y, a0, c0), fmaf(v.y, a1, c1));
        r.z = fmaxf(fmaf(v.z, a0, c0), fmaf(v.z, a1, c1));
        r.w = fmaxf(fmaf(v.w, a0, c0), fmaf(v.w, a1, c1));
        op[i] = r;
    }
    if (lane < 16) {
        float4 v = xp[768 + lane];
        float4 r;
        r.x = fmaxf(fmaf(v.x, a0, c0), fmaf(v.x, a1, c1));
        r.y = fmaxf(fmaf(v.y, a0, c0), fmaf(v.y, a1, c1));
        r.z = fmaxf(fmaf(v.z, a0, c0), fmaf(v.z, a1, c1));
        r.w = fmaxf(fmaf(v.w, a0, c0), fmaf(v.w, a1, c1));
        op[768 + lane] = r;
    }
}

extern "C" void kernel_launch(void* const* d_in, const int* in_sizes, int n_in,
                              void* d_out, int out_size) {
    const float* x      = (const float*)d_in[0];
    const float* fc1_w  = (const float*)d_in[1];
    const float* fc1_b  = (const float*)d_in[2];
    const float* fc2_w  = (const float*)d_in[3];
    const float* fc2_b  = (const float*)d_in[4];
    float* out = (float*)d_out;

    pool_kernel<<<NPLANE / 8, 256>>>(x);
    coef_kernel<<<KK * BB, 256>>>(fc1_w, fc1_b, fc2_w, fc2_b);
    apply_kernel<<<NPLANE / 8, 256>>>(x, out);
}